// round 17
// baseline (speedup 1.0000x reference)
#include <cuda_runtime.h>
#include <cuda_fp16.h>
#include <stdint.h>
#include <math.h>

// Fixed shapes
#define CDIM   64
#define HW     4096                 // 64*64
#define KCODES 512
#define NPTS   131072               // 32*4096
#define NQ     (NPTS*CDIM)          // 8388608
// Output layout: [loss(1) | quantized(NQ) | perplexity(1) | indices(NPTS)]
#define QOFF   1
#define POFF   (1+NQ)
#define IOFF   (2+NQ)

#define TPB      128                // 4 warps
#define PTS_WARP 32                 // two 16-pt A-sets per warp
#define PTS_CTA  128
#define NCTA     (NPTS/PTS_CTA)     // 1024
#define NCT      (KCODES/8)         // 64 code tiles of 8

// B fp16 fragments, prep-split hi/lo, fragment order, coalesced:
// [ct][qq(0..3)][lane] uint4.  qq: 0=hi kb0-1, 1=hi kb2-3, 2=lo kb0-1, 3=lo kb2-3
// +2 tiles padding for prefetch overrun.
__device__ uint4  g_B[(NCT+2)*4*32];
__device__ float4 g_ET[KCODES*16];   // row-major codebook eT[k][c] as float4
__device__ float  g_se2[KCODES];
__device__ int    g_counts[KCODES];
__device__ float  g_loss;
__device__ int    g_done;

__device__ __forceinline__ unsigned packh2(float x, float y) {
    __half2 h = __floats2half2_rn(x, y);
    return *(unsigned*)&h;
}
// split v into fp16 hi + fp16 lo (v ~= hi + lo, residual ~2^-22 |v|)
__device__ __forceinline__ void split2(float x, float y,
                                       unsigned& hi, unsigned& lo) {
    __half hx = __float2half_rn(x), hy = __float2half_rn(y);
    float  rx = x - __half2float(hx), ry = y - __half2float(hy);
    __half2 h = __halves2half2(hx, hy);
    hi = *(unsigned*)&h;
    lo = packh2(rx, ry);
}

#define MMA_F16(d0,d1,d2,d3, a0,a1,a2,a3, b0,b1)                               \
    asm("mma.sync.aligned.m16n8k16.row.col.f32.f16.f16.f32 "                   \
        "{%0,%1,%2,%3}, {%4,%5,%6,%7}, {%8,%9}, {%0,%1,%2,%3};"                \
        : "+f"(d0), "+f"(d1), "+f"(d2), "+f"(d3)                               \
        : "r"(a0), "r"(a1), "r"(a2), "r"(a3), "r"(b0), "r"(b1))

// ---------------- prep: B fp16 hi/lo fragments, eT, se2, zeros ---------------
__global__ void __launch_bounds__(256)
vq_prep(const float* __restrict__ emb) {
    int id = blockIdx.x * 256 + threadIdx.x;
    if (id < NCT*4*32) {
        int ct   = id >> 7;
        int qq   = (id >> 5) & 3;
        int lane = id & 31;
        int g = lane >> 2, t = lane & 3;
        int split = qq >> 1, halfp = qq & 1;
        int code  = ct*8 + g;
        unsigned v[4];
        #pragma unroll
        for (int comp = 0; comp < 4; comp++) {
            int kb = halfp*2 + (comp >> 1);
            int r  = comp & 1;
            int c0 = kb*16 + 2*t + r*8;       // b-reg r: K rows 2t(+8), 2t+1(+8)
            float f0 = emb[c0*KCODES + code];
            float f1 = emb[(c0+1)*KCODES + code];
            unsigned hi, lo;
            split2(f0, f1, hi, lo);
            v[comp] = split ? lo : hi;
        }
        g_B[(ct*4 + qq)*32 + lane] = make_uint4(v[0], v[1], v[2], v[3]);
    } else if (id < NCT*4*32 + KCODES*16) {
        int id2 = id - NCT*4*32;
        int k  = id2 >> 4;
        int c4 = id2 & 15;
        g_ET[k*16 + c4] = make_float4(emb[(c4*4+0)*KCODES + k],
                                      emb[(c4*4+1)*KCODES + k],
                                      emb[(c4*4+2)*KCODES + k],
                                      emb[(c4*4+3)*KCODES + k]);
    } else if (id < NCT*4*32 + KCODES*16 + KCODES) {
        int k = id - NCT*4*32 - KCODES*16;
        float s = 0.0f;
        #pragma unroll 8
        for (int c = 0; c < CDIM; c++) {
            float v = emb[c*KCODES + k];
            s = fmaf(v, v, s);
        }
        g_se2[k] = s;
        g_counts[k] = 0;
        if (k == 0) { g_loss = 0.0f; g_done = 0; }
    }
}

// ---------------- main: distances + argmin + fused quantized write -----------

#define PREFETCH(CT, BF)                                                       \
    { _Pragma("unroll")                                                        \
      for (int m = 0; m < 4; m++) BF[m] = Bp[((CT)*4 + m)*32 + lane]; }

// one 16-point A-set against tile CT
#define TILE_SET(CT, BF, AH, AL, BEST0, BEST1, BI0, BI1)                       \
    {                                                                          \
        float hh0=0.f,hh1=0.f,hh2=0.f,hh3=0.f;                                 \
        float hl0=0.f,hl1=0.f,hl2=0.f,hl3=0.f;                                 \
        float lh0=0.f,lh1=0.f,lh2=0.f,lh3=0.f;                                 \
        _Pragma("unroll")                                                      \
        for (int kb = 0; kb < 4; kb++) {                                       \
            uint4 H = BF[kb>>1];                                               \
            uint4 L = BF[2 + (kb>>1)];                                         \
            unsigned bh0, bh1, bl0, bl1;                                       \
            if ((kb & 1) == 0) { bh0=H.x; bh1=H.y; bl0=L.x; bl1=L.y; }         \
            else               { bh0=H.z; bh1=H.w; bl0=L.z; bl1=L.w; }         \
            MMA_F16(hh0,hh1,hh2,hh3,                                           \
                    AH[kb*4+0],AH[kb*4+1],AH[kb*4+2],AH[kb*4+3], bh0,bh1);     \
            MMA_F16(hl0,hl1,hl2,hl3,                                           \
                    AH[kb*4+0],AH[kb*4+1],AH[kb*4+2],AH[kb*4+3], bl0,bl1);     \
            MMA_F16(lh0,lh1,lh2,lh3,                                           \
                    AL[kb*4+0],AL[kb*4+1],AL[kb*4+2],AL[kb*4+3], bh0,bh1);     \
        }                                                                      \
        float d0 = (hh0 + hl0) + lh0;                                          \
        float d1 = (hh1 + hl1) + lh1;                                          \
        float d2 = (hh2 + hl2) + lh2;                                          \
        float d3 = (hh3 + hl3) + lh3;                                          \
        int col = (CT)*8 + 2*t;                                                \
        float s0 = sse2[col], s1 = sse2[col+1];                                \
        float q0 = fmaf(-2.0f, d0, s0);                                        \
        float q1 = fmaf(-2.0f, d1, s1);                                        \
        float q2 = fmaf(-2.0f, d2, s0);                                        \
        float q3 = fmaf(-2.0f, d3, s1);                                        \
        if (q0 < BEST0 || (q0 == BEST0 && col   < BI0)) { BEST0 = q0; BI0 = col;   } \
        if (q1 < BEST0 || (q1 == BEST0 && col+1 < BI0)) { BEST0 = q1; BI0 = col+1; } \
        if (q2 < BEST1 || (q2 == BEST1 && col   < BI1)) { BEST1 = q2; BI1 = col;   } \
        if (q3 < BEST1 || (q3 == BEST1 && col+1 < BI1)) { BEST1 = q3; BI1 = col+1; } \
    }

// load one 16-point A-set (base pointer PB) into AH/AL, accumulating zsq
#define LOAD_ASET(PB, AH, AL, ZS0, ZS1)                                        \
    { _Pragma("unroll")                                                        \
      for (int kb = 0; kb < 4; kb++) {                                         \
        int cb = kb*16 + 2*t;                                                  \
        float f00 = (PB)[g     + (size_t)(cb    ) * HW];                       \
        float f01 = (PB)[g     + (size_t)(cb + 1) * HW];                       \
        float f10 = (PB)[g + 8 + (size_t)(cb    ) * HW];                       \
        float f11 = (PB)[g + 8 + (size_t)(cb + 1) * HW];                       \
        float f20 = (PB)[g     + (size_t)(cb + 8) * HW];                       \
        float f21 = (PB)[g     + (size_t)(cb + 9) * HW];                       \
        float f30 = (PB)[g + 8 + (size_t)(cb + 8) * HW];                       \
        float f31 = (PB)[g + 8 + (size_t)(cb + 9) * HW];                       \
        ZS0 = fmaf(f00,f00, fmaf(f01,f01, fmaf(f20,f20, fmaf(f21,f21, ZS0)))); \
        ZS1 = fmaf(f10,f10, fmaf(f11,f11, fmaf(f30,f30, fmaf(f31,f31, ZS1)))); \
        split2(f00, f01, AH[kb*4+0], AL[kb*4+0]);                              \
        split2(f10, f11, AH[kb*4+1], AL[kb*4+1]);                              \
        split2(f20, f21, AH[kb*4+2], AL[kb*4+2]);                              \
        split2(f30, f31, AH[kb*4+3], AL[kb*4+3]);                              \
      } }

__global__ void __launch_bounds__(TPB)
vq_main(const float* __restrict__ x, float* __restrict__ out) {
    __shared__ float sse2[KCODES];
    __shared__ int   shist[KCODES];
    __shared__ int   sbi[PTS_CTA];
    __shared__ float wred[4];
    __shared__ float ws2[4];

    const int tid  = threadIdx.x;
    const int warp = tid >> 5;
    const int lane = tid & 31;
    const int g    = lane >> 2;
    const int t    = lane & 3;

    #pragma unroll
    for (int i = 0; i < 4; i++) {
        sse2[tid + i*TPB]  = g_se2[tid + i*TPB];
        shist[tid + i*TPB] = 0;
    }

    // ---- load this warp's 32 points as two fp16-split A-fragment sets ------
    const int p0w = blockIdx.x * PTS_CTA + warp * PTS_WARP;
    const int b   = p0w >> 12;
    const int hw  = p0w & (HW - 1);        // multiple of 32, +31 stays in block
    const float* BaseA = x + (size_t)b * CDIM * HW + hw;
    const float* BaseB = BaseA + 16;

    unsigned ahA[16], alA[16], ahB[16], alB[16];
    float zA0 = 0.f, zA1 = 0.f, zB0 = 0.f, zB1 = 0.f;
    LOAD_ASET(BaseA, ahA, alA, zA0, zA1);
    LOAD_ASET(BaseB, ahB, alB, zB0, zB1);
    __syncthreads();

    // ---- 64 code tiles; each B-fragment load feeds both A-sets -------------
    float bA0 = 3.4e38f, bA1 = 3.4e38f, bB0 = 3.4e38f, bB1 = 3.4e38f;
    int   iA0 = 0, iA1 = 0, iB0 = 0, iB1 = 0;
    const uint4* Bp = g_B;

    uint4 B0[4], B1[4];
    PREFETCH(0, B0);
    #pragma unroll 1
    for (int ct = 0; ct < NCT; ct += 2) {
        PREFETCH(ct+1, B1);
        TILE_SET(ct, B0, ahA, alA, bA0, bA1, iA0, iA1);
        TILE_SET(ct, B0, ahB, alB, bB0, bB1, iB0, iB1);
        PREFETCH(ct+2, B0);       // ct=62 -> tile 64 = padding, safe
        TILE_SET(ct+1, B1, ahA, alA, bA0, bA1, iA0, iA1);
        TILE_SET(ct+1, B1, ahB, alB, bB0, bB1, iB0, iB1);
    }

    // ---- reduce across the 4 threads of each group --------------------------
    #pragma unroll
    for (int off = 1; off <= 2; off <<= 1) {
        float o0 = __shfl_xor_sync(0xffffffffu, bA0, off);
        int   j0 = __shfl_xor_sync(0xffffffffu, iA0, off);
        float o1 = __shfl_xor_sync(0xffffffffu, bA1, off);
        int   j1 = __shfl_xor_sync(0xffffffffu, iA1, off);
        float o2 = __shfl_xor_sync(0xffffffffu, bB0, off);
        int   j2 = __shfl_xor_sync(0xffffffffu, iB0, off);
        float o3 = __shfl_xor_sync(0xffffffffu, bB1, off);
        int   j3 = __shfl_xor_sync(0xffffffffu, iB1, off);
        float zo0 = __shfl_xor_sync(0xffffffffu, zA0, off);
        float zo1 = __shfl_xor_sync(0xffffffffu, zA1, off);
        float zo2 = __shfl_xor_sync(0xffffffffu, zB0, off);
        float zo3 = __shfl_xor_sync(0xffffffffu, zB1, off);
        if (o0 < bA0 || (o0 == bA0 && j0 < iA0)) { bA0 = o0; iA0 = j0; }
        if (o1 < bA1 || (o1 == bA1 && j1 < iA1)) { bA1 = o1; iA1 = j1; }
        if (o2 < bB0 || (o2 == bB0 && j2 < iB0)) { bB0 = o2; iB0 = j2; }
        if (o3 < bB1 || (o3 == bB1 && j3 < iB1)) { bB1 = o3; iB1 = j3; }
        zA0 += zo0; zA1 += zo1; zB0 += zo2; zB1 += zo3;
    }

    // ---- emit indices, hist, loss partial, stage bi -------------------------
    float lsum = 0.0f;
    const int wbase = warp * PTS_WARP;
    if (t == 0) {
        out[IOFF + p0w + g]      = (float)iA0;
        out[IOFF + p0w + g + 8]  = (float)iA1;
        out[IOFF + p0w + g + 16] = (float)iB0;
        out[IOFF + p0w + g + 24] = (float)iB1;
        sbi[wbase + g]      = iA0;
        sbi[wbase + g + 8]  = iA1;
        sbi[wbase + g + 16] = iB0;
        sbi[wbase + g + 24] = iB1;
        atomicAdd(&shist[iA0], 1);
        atomicAdd(&shist[iA1], 1);
        atomicAdd(&shist[iB0], 1);
        atomicAdd(&shist[iB1], 1);
        lsum = ((bA0 + zA0) + (bA1 + zA1)) + ((bB0 + zB0) + (bB1 + zB1));
    }
    #pragma unroll
    for (int o = 16; o > 0; o >>= 1)
        lsum += __shfl_down_sync(0xffffffffu, lsum, o);
    if (lane == 0) wred[warp] = lsum;
    __syncwarp();

    // ---- fused quantized write: lane = one of the warp's 32 points ----------
    {
        const int bi = sbi[wbase + lane];
        float* oq = out + QOFF + (size_t)b * CDIM * HW + hw + lane;
        const float4* er = g_ET + bi * 16;
        #pragma unroll 4
        for (int i = 0; i < 16; i++) {
            float4 e4 = er[i];
            oq[(size_t)(4*i  ) * HW] = e4.x;
            oq[(size_t)(4*i+1) * HW] = e4.y;
            oq[(size_t)(4*i+2) * HW] = e4.z;
            oq[(size_t)(4*i+3) * HW] = e4.w;
        }
    }

    __syncthreads();
    // flush hist + loss
    #pragma unroll
    for (int i = 0; i < 4; i++) {
        int h = shist[tid + i*TPB];
        if (h) atomicAdd(&g_counts[tid + i*TPB], h);
    }
    if (tid < 4) {
        float v = wred[tid];
        #pragma unroll
        for (int o = 2; o > 0; o >>= 1)
            v += __shfl_down_sync(0xfu, v, o);
        if (tid == 0) atomicAdd(&g_loss, v);
    }

    // ---- last CTA finalizes loss + perplexity -------------------------------
    __syncthreads();
    __threadfence();
    __shared__ int s_rank;
    if (tid == 0) s_rank = atomicAdd(&g_done, 1);
    __syncthreads();
    if (s_rank == NCTA - 1) {
        float v = 0.0f;
        #pragma unroll
        for (int k = tid; k < KCODES; k += TPB) {
            float pr = (float)g_counts[k] * (1.0f / (float)NPTS);
            v += pr * logf(pr + 1e-10f);
        }
        #pragma unroll
        for (int o = 16; o > 0; o >>= 1)
            v += __shfl_down_sync(0xffffffffu, v, o);
        if (lane == 0) ws2[warp] = v;
        __syncthreads();
        if (tid == 0) {
            float s = (ws2[0] + ws2[1]) + (ws2[2] + ws2[3]);
            // loss = q_latent + 0.25*e_latent; both equal mean((q-z)^2)
            out[0]    = g_loss * (1.25f / (float)NQ);
            out[POFF] = expf(-s);
        }
    }
}

extern "C" void kernel_launch(void* const* d_in, const int* in_sizes, int n_in,
                              void* d_out, int out_size) {
    const float* x   = (const float*)d_in[0];
    const float* emb = (const float*)d_in[1];
    float* out = (float*)d_out;

    vq_prep<<<(NCT*4*32 + KCODES*16 + KCODES + 255)/256, 256>>>(emb);
    vq_main<<<NCTA, TPB>>>(x, out);
}